// round 3
// baseline (speedup 1.0000x reference)
#include <cuda_runtime.h>
#include <cuda_fp16.h>

// Problem constants
#define MM        16
#define NN        8192
#define KK        8192
#define GS        128
#define KSPLIT    64            // KK / GS : one scale group per CTA
#define NTILES    8             // NN / (TPB * CPT)
#define TPB       256
#define CPT       4             // columns per thread
#define WPG       16            // packed words per group (GS / 8)

// 64 * 16 * 8192 floats = 32 MiB partials (allocation-free scratch)
__device__ float g_scratch[(size_t)KSPLIT * MM * NN];

// ---- packed f32x2 helpers (Blackwell FFMA2 path, PTX-only) ----
static __device__ __forceinline__ unsigned long long pack2(unsigned int v) {
    unsigned long long r;
    asm("mov.b64 %0, {%1, %1};" : "=l"(r) : "r"(v));
    return r;
}
static __device__ __forceinline__ unsigned long long fadd2(unsigned long long a,
                                                           unsigned long long b) {
    unsigned long long d;
    asm("add.rn.f32x2 %0, %1, %2;" : "=l"(d) : "l"(a), "l"(b));
    return d;
}
static __device__ __forceinline__ void ffma2(unsigned long long& acc,
                                             unsigned long long a,
                                             unsigned long long b) {
    asm("fma.rn.f32x2 %0, %1, %2, %0;" : "+l"(acc) : "l"(a), "l"(b));
}

// Stage 1: per (N-tile, K-group) CTA computes scaled group partials into scratch.
__global__ void __launch_bounds__(TPB)
fp4gemm_stage1(const float* __restrict__ x,       // [16, 8192] f32
               const int*   __restrict__ wp,      // [1024, 8192] packed FP4
               const float* __restrict__ scales)  // [64, 8192] f32
{
    __shared__ __align__(16) float xs[GS * MM];   // [k_local][m], 8 KiB

    const int tid   = threadIdx.x;
    const int ntile = blockIdx.x;
    const int ks    = blockIdx.y;
    const int kbase = ks * GS;

    // Cooperative stage of x chunk, layout [k][m] so m-pairs are contiguous
    // 8B for broadcast LDS.64.
    for (int idx = tid; idx < GS * MM; idx += TPB) {
        const int k = idx >> 4;
        const int m = idx & 15;
        xs[idx] = x[m * KK + kbase + k];
    }
    __syncthreads();

    unsigned long long acc[CPT][8];
    #pragma unroll
    for (int c = 0; c < CPT; ++c)
        #pragma unroll
        for (int p = 0; p < 8; ++p)
            acc[c][p] = 0ull;

    const int col0 = ntile * (TPB * CPT) + tid;
    const int kp0  = ks * WPG;
    // (2^23 + q) + (-2^23 - 8) = q - 8 : de-bias and zero-point in one FADD2
    const unsigned long long bias = pack2(__float_as_uint(-8388616.0f));

    // software-pipelined weight-word prefetch
    unsigned int w[CPT];
    #pragma unroll
    for (int c = 0; c < CPT; ++c)
        w[c] = (unsigned int)wp[(size_t)kp0 * NN + col0 + c * TPB];

    #pragma unroll 1
    for (int i = 0; i < WPG; ++i) {
        unsigned int wn[CPT];
        if (i + 1 < WPG) {
            #pragma unroll
            for (int c = 0; c < CPT; ++c)
                wn[c] = (unsigned int)wp[(size_t)(kp0 + i + 1) * NN + col0 + c * TPB];
        } else {
            #pragma unroll
            for (int c = 0; c < CPT; ++c) wn[c] = 0u;
        }

        #pragma unroll
        for (int j = 0; j < 8; ++j) {
            // broadcast x pairs for k = i*8 + j (shared across the 4 columns)
            const unsigned long long* xr =
                reinterpret_cast<const unsigned long long*>(&xs[(i * 8 + j) * MM]);
            unsigned long long xv[8];
            #pragma unroll
            for (int p = 0; p < 8; ++p) xv[p] = xr[p];

            #pragma unroll
            for (int c = 0; c < CPT; ++c) {
                const unsigned int nib = (w[c] >> (4 * j)) & 15u;
                const unsigned long long q2 =
                    fadd2(pack2(0x4B000000u | nib), bias);   // (q-8, q-8)
                #pragma unroll
                for (int p = 0; p < 8; ++p) ffma2(acc[c][p], xv[p], q2);
            }
        }

        #pragma unroll
        for (int c = 0; c < CPT; ++c) w[c] = wn[c];
    }

    // Epilogue: apply 0.5 * scale for this group, write partials.
    #pragma unroll
    for (int c = 0; c < CPT; ++c) {
        const int col = col0 + c * TPB;
        const float s = 0.5f * scales[ks * NN + col];
        float* dst = &g_scratch[(size_t)ks * MM * NN + col];
        #pragma unroll
        for (int p = 0; p < 8; ++p) {
            unsigned int lo, hi;
            asm("mov.b64 {%0, %1}, %2;" : "=r"(lo), "=r"(hi) : "l"(acc[c][p]));
            dst[(size_t)(2 * p)     * NN] = __uint_as_float(lo) * s;
            dst[(size_t)(2 * p + 1) * NN] = __uint_as_float(hi) * s;
        }
    }
}

// Stage 2: deterministic reduction of 64 K-split partials.
// Reference emits fp16 then upcasts -> round through half, store as f32.
__global__ void __launch_bounds__(TPB)
fp4gemm_reduce(float* __restrict__ out)
{
    const int idx = blockIdx.x * TPB + threadIdx.x;   // idx = m*NN + n
    const int n = idx & (NN - 1);
    const int m = idx >> 13;
    float s = 0.0f;
    #pragma unroll
    for (int ks = 0; ks < KSPLIT; ++ks)
        s += g_scratch[((size_t)(ks * MM + m)) * NN + n];
    out[idx] = __half2float(__float2half(s));
}

extern "C" void kernel_launch(void* const* d_in, const int* in_sizes, int n_in,
                              void* d_out, int out_size)
{
    const float* x      = (const float*)d_in[0];   // [16, 8192] f32 (harness-promoted)
    const int*   wp     = (const int*)  d_in[1];   // [1024, 8192] int32 packed FP4
    const float* scales = (const float*)d_in[2];   // [64, 8192] f32 (harness-promoted)
    float*       out    = (float*)d_out;           // [16, 8192] f32 (half-rounded values)

    dim3 grid1(NTILES, KSPLIT);
    fp4gemm_stage1<<<grid1, TPB>>>(x, wp, scales);
    fp4gemm_reduce<<<(MM * NN) / TPB, TPB>>>(out);
}

// round 6
// speedup vs baseline: 2.2511x; 2.2511x over previous
#include <cuda_runtime.h>
#include <cuda_fp16.h>
#include <cstdint>

// ---------------- problem constants ----------------
#define MM      16
#define NN      8192
#define KK      8192
#define GS      128
#define KSPLIT  16
#define KRANGE  (KK / KSPLIT)        // 512 k per CTA
#define KBLKS   (KRANGE / 16)        // 32 k16-blocks
#define TPB     256                  // 8 warps
#define WCOLS   64                   // columns per warp (8 n-tiles of 8)
#define CTACOLS 512
#define NCTA_N  (NN / CTACOLS)       // 16
#define XS_STRIDE 520                // 512 + 8 halves pad (conflict-free LDS)

// 16 * 16 * 8192 f32 = 8 MiB K-split partials
__device__ float g_part[(size_t)KSPLIT * MM * NN];

// nibble-pair (2c, 2c+1) -> scaled fp16x2: (q-8) * (0.5*scale), single rounding.
// BFE isolates the byte so the (t | t<<12) merge has no high-nibble pollution.
static __device__ __forceinline__ __half2 dq16(uint32_t w, uint32_t sh8, __half2 s2) {
    uint32_t t;
    asm("bfe.u32 %0, %1, %2, 8;" : "=r"(t) : "r"(w), "r"(sh8)); // nib2c @0..3, nib2c+1 @4..7
    uint32_t v;
    // v = (t | (t<<12)) & 0x000F000F   (LUT 0xA8 = (a|b)&c); t's bits >7 are zero
    asm("lop3.b32 %0, %1, %2, 0x000F000F, 0xA8;" : "=r"(v) : "r"(t), "r"(t << 12));
    v |= 0x64006400u;                 // fp16x2 (1024+q_lo, 1024+q_hi), exact
    const uint32_t m1032 = 0xE408E408u;   // fp16x2 (-1032, -1032)
    __half2 h = __hadd2(*reinterpret_cast<__half2*>(&v),
                        *reinterpret_cast<const __half2*>(&m1032)); // (q-8) exact
    return __hmul2(h, s2);
}

static __device__ __forceinline__ void hmma16816(float* d, uint32_t a0, uint32_t a1,
                                                 uint32_t a2, uint32_t a3,
                                                 uint32_t b0, uint32_t b1) {
    asm volatile(
        "mma.sync.aligned.m16n8k16.row.col.f32.f16.f16.f32 "
        "{%0,%1,%2,%3}, {%4,%5,%6,%7}, {%8,%9}, {%0,%1,%2,%3};"
        : "+f"(d[0]), "+f"(d[1]), "+f"(d[2]), "+f"(d[3])
        : "r"(a0), "r"(a1), "r"(a2), "r"(a3), "r"(b0), "r"(b1));
}

// ---------------- stage 1: dequant-to-register + HMMA ----------------
__global__ void __launch_bounds__(TPB, 2)
fp4hmma_stage1(const float* __restrict__ x,       // [16, 8192] f32 (exact fp16 values)
               const int*   __restrict__ wp,      // [1024, 8192] int32 packed FP4
               const float* __restrict__ scales)  // [64, 8192] f32 (exact fp16 values)
{
    __shared__ __align__(16) __half xs[MM][XS_STRIDE];

    const int tid  = threadIdx.x;
    const int wrp  = tid >> 5;
    const int lane = tid & 31;
    const int g    = lane >> 2;       // 0..7 : A-row / B-col / D-row
    const int c    = lane & 3;        // 0..3 : k-pair selector
    const int kb0  = blockIdx.y * KRANGE;

    // ---- stage x chunk [16 x 512] as fp16 (exact convert) ----
    #pragma unroll
    for (int it = 0; it < 8; ++it) {
        const int p  = tid + it * TPB;        // float4 slot 0..2047
        const int m  = p >> 7;                // 128 float4 per row
        const int k4 = (p & 127) << 2;
        const float4 v = *(const float4*)&x[(size_t)m * KK + kb0 + k4];
        *(__half2*)&xs[m][k4]     = __floats2half2_rn(v.x, v.y);
        *(__half2*)&xs[m][k4 + 2] = __floats2half2_rn(v.z, v.w);
    }
    __syncthreads();

    const int wb = blockIdx.x * CTACOLS + wrp * WCOLS;   // warp column base

    float acc[8][4];
    #pragma unroll
    for (int t = 0; t < 8; ++t)
        #pragma unroll
        for (int r = 0; r < 4; ++r) acc[t][r] = 0.0f;

    __half2 s2[8];
    const uint32_t sh8   = (uint32_t)c * 8u;
    const int      prow0 = blockIdx.y * (KRANGE / 8);    // packed-word row base

    for (int kb = 0; kb < KBLKS; ++kb) {
        // per-group scales (group == 128 k == 8 k-blocks)
        if ((kb & 7) == 0) {
            const int grp = blockIdx.y * (KRANGE / GS) + (kb >> 3);
            #pragma unroll
            for (int t = 0; t < 8; ++t) {
                const float s = scales[(size_t)grp * NN + wb + t * 8 + g];
                s2[t] = __half2half2(__float2half_rn(0.5f * s));
            }
        }

        // A fragments from SMEM (conflict-free: bank = (4g + c) % 32, all distinct)
        const int klo = kb * 16 + c * 2;
        const uint32_t a0 = *(const uint32_t*)&xs[g][klo];          // (g,   klo..+1)
        const uint32_t a1 = *(const uint32_t*)&xs[g + 8][klo];      // (g+8, klo..+1)
        const uint32_t a2 = *(const uint32_t*)&xs[g][klo + 8];      // (g,   klo+8..)
        const uint32_t a3 = *(const uint32_t*)&xs[g + 8][klo + 8];  // (g+8, klo+8..)

        // batch the 16 weight-word loads (MLP)
        const int* wr0 = &wp[(size_t)(prow0 + kb * 2) * NN + wb + g];
        const int* wr1 = wr0 + NN;
        uint32_t w0[8], w1[8];
        #pragma unroll
        for (int t = 0; t < 8; ++t) { w0[t] = (uint32_t)wr0[t * 8];
                                      w1[t] = (uint32_t)wr1[t * 8]; }

        #pragma unroll
        for (int t = 0; t < 8; ++t) {
            const __half2 b0 = dq16(w0[t], sh8, s2[t]);   // k 2c,2c+1
            const __half2 b1 = dq16(w1[t], sh8, s2[t]);   // k 2c+8,2c+9
            hmma16816(acc[t], a0, a1, a2, a3,
                      *(const uint32_t*)&b0, *(const uint32_t*)&b1);
        }
    }

    // ---- epilogue: write K-split partials ----
    const size_t pbase = (size_t)blockIdx.y * MM * NN;
    #pragma unroll
    for (int t = 0; t < 8; ++t) {
        const int n = wb + t * 8 + c * 2;
        *(float2*)&g_part[pbase + (size_t)g * NN + n]       = make_float2(acc[t][0], acc[t][1]);
        *(float2*)&g_part[pbase + (size_t)(g + 8) * NN + n] = make_float2(acc[t][2], acc[t][3]);
    }
}

// ---------------- stage 2: sum 16 K-split partials, round through fp16 ----------------
__global__ void __launch_bounds__(256)
fp4hmma_reduce(float* __restrict__ out)
{
    const int idx = blockIdx.x * 256 + threadIdx.x;   // m*NN + n
    float s = 0.0f;
    #pragma unroll
    for (int i = 0; i < KSPLIT; ++i)
        s += g_part[(size_t)i * MM * NN + idx];
    out[idx] = __half2float(__float2half(s));
}

extern "C" void kernel_launch(void* const* d_in, const int* in_sizes, int n_in,
                              void* d_out, int out_size)
{
    const float* x      = (const float*)d_in[0];
    const int*   wp     = (const int*)  d_in[1];
    const float* scales = (const float*)d_in[2];
    float*       out    = (float*)d_out;

    dim3 grid(NCTA_N, KSPLIT);
    fp4hmma_stage1<<<grid, TPB>>>(x, wp, scales);
    fp4hmma_reduce<<<(MM * NN) / 256, 256>>>(out);
}

// round 7
// speedup vs baseline: 2.2585x; 1.0033x over previous
#include <cuda_runtime.h>
#include <cuda_fp16.h>
#include <cstdint>

// ---------------- problem constants ----------------
#define MM      16
#define NN      8192
#define KK      8192
#define GS      128
#define KSPLIT  16
#define KRANGE  (KK / KSPLIT)        // 512 k per CTA
#define KBLKS   (KRANGE / 16)        // 32 k16-blocks
#define NGRP    (KRANGE / GS)        // 4 scale groups per CTA
#define TPB     256                  // 8 warps
#define WCOLS   64                   // columns per warp (8 n-tiles of 8)
#define CTACOLS 512
#define NCTA_N  (NN / CTACOLS)       // 16
#define XS_STRIDE 520                // 512 + 8 halves pad (conflict-free LDS)

// 16 * 16 * 8192 f32 = 8 MiB K-split partials
__device__ float g_part[(size_t)KSPLIT * MM * NN];

// nibble-pair (2c, 2c+1) -> scaled fp16x2: (q-8) * (0.5*scale), single rounding.
static __device__ __forceinline__ __half2 dq16(uint32_t w, uint32_t sh8, __half2 s2) {
    uint32_t t;
    asm("bfe.u32 %0, %1, %2, 8;" : "=r"(t) : "r"(w), "r"(sh8)); // clean byte extract
    uint32_t v;
    asm("lop3.b32 %0, %1, %2, 0x000F000F, 0xA8;" : "=r"(v) : "r"(t), "r"(t << 12));
    v |= 0x64006400u;                 // fp16x2 (1024+q_lo, 1024+q_hi), exact
    const uint32_t m1032 = 0xE408E408u;   // fp16x2 (-1032, -1032)
    __half2 h = __hadd2(*reinterpret_cast<__half2*>(&v),
                        *reinterpret_cast<const __half2*>(&m1032)); // (q-8) exact
    return __hmul2(h, s2);
}

static __device__ __forceinline__ void hmma16816(float* d, uint32_t a0, uint32_t a1,
                                                 uint32_t a2, uint32_t a3,
                                                 uint32_t b0, uint32_t b1) {
    asm volatile(
        "mma.sync.aligned.m16n8k16.row.col.f32.f16.f16.f32 "
        "{%0,%1,%2,%3}, {%4,%5,%6,%7}, {%8,%9}, {%0,%1,%2,%3};"
        : "+f"(d[0]), "+f"(d[1]), "+f"(d[2]), "+f"(d[3])
        : "r"(a0), "r"(a1), "r"(a2), "r"(a3), "r"(b0), "r"(b1));
}

// ---------------- stage 1: dequant-to-register + HMMA, software pipelined ----------------
__global__ void __launch_bounds__(TPB, 2)
fp4hmma_stage1(const float* __restrict__ x,       // [16, 8192] f32 (exact fp16 values)
               const int*   __restrict__ wp,      // [1024, 8192] int32 packed FP4
               const float* __restrict__ scales)  // [64, 8192] f32 (exact fp16 values)
{
    __shared__ __align__(16) __half xs[MM][XS_STRIDE];

    const int tid  = threadIdx.x;
    const int wrp  = tid >> 5;
    const int lane = tid & 31;
    const int g    = lane >> 2;       // 0..7 : A-row / B-col / D-row
    const int c    = lane & 3;        // 0..3 : k-pair selector
    const int kb0  = blockIdx.y * KRANGE;

    // ---- stage x chunk [16 x 512] as fp16 (exact convert) ----
    #pragma unroll
    for (int it = 0; it < 8; ++it) {
        const int p  = tid + it * TPB;
        const int m  = p >> 7;
        const int k4 = (p & 127) << 2;
        const float4 v = *(const float4*)&x[(size_t)m * KK + kb0 + k4];
        *(__half2*)&xs[m][k4]     = __floats2half2_rn(v.x, v.y);
        *(__half2*)&xs[m][k4 + 2] = __floats2half2_rn(v.z, v.w);
    }
    __syncthreads();

    const int wb = blockIdx.x * CTACOLS + wrp * WCOLS;   // warp column base

    float acc[8][4];
    #pragma unroll
    for (int t = 0; t < 8; ++t)
        #pragma unroll
        for (int r = 0; r < 4; ++r) acc[t][r] = 0.0f;

    const uint32_t sh8   = (uint32_t)c * 8u;
    const int      prow0 = blockIdx.y * (KRANGE / 8);    // packed-word row base

    // ---- prologue: prefetch scales (group 0) and weights (kb 0) ----
    float snext[8];
    #pragma unroll
    for (int t = 0; t < 8; ++t)
        snext[t] = scales[(size_t)(blockIdx.y * NGRP) * NN + wb + t * 8 + g];

    uint32_t w0[8], w1[8];
    {
        const int* r0 = &wp[(size_t)prow0 * NN + wb + g];
        const int* r1 = r0 + NN;
        #pragma unroll
        for (int t = 0; t < 8; ++t) { w0[t] = (uint32_t)r0[t * 8];
                                      w1[t] = (uint32_t)r1[t * 8]; }
    }

    __half2 s2[8];

    for (int kb = 0; kb < KBLKS; ++kb) {
        // group boundary: convert prefetched scales, prefetch next group's
        if ((kb & 7) == 0) {
            #pragma unroll
            for (int t = 0; t < 8; ++t)
                s2[t] = __half2half2(__float2half_rn(0.5f * snext[t]));
            const int gn  = ((kb >> 3) + 1 < NGRP) ? (kb >> 3) + 1 : (kb >> 3);
            const size_t grow = (size_t)(blockIdx.y * NGRP + gn) * NN;
            #pragma unroll
            for (int t = 0; t < 8; ++t)
                snext[t] = scales[grow + wb + t * 8 + g];
        }

        // prefetch weights for kb+1 (clamped) BEFORE consuming current ones
        const int kbn = (kb + 1 < KBLKS) ? kb + 1 : kb;
        uint32_t wn0[8], wn1[8];
        {
            const int* r0 = &wp[(size_t)(prow0 + kbn * 2) * NN + wb + g];
            const int* r1 = r0 + NN;
            #pragma unroll
            for (int t = 0; t < 8; ++t) { wn0[t] = (uint32_t)r0[t * 8];
                                          wn1[t] = (uint32_t)r1[t * 8]; }
        }

        // A fragments from SMEM (conflict-free)
        const int klo = kb * 16 + c * 2;
        const uint32_t a0 = *(const uint32_t*)&xs[g][klo];
        const uint32_t a1 = *(const uint32_t*)&xs[g + 8][klo];
        const uint32_t a2 = *(const uint32_t*)&xs[g][klo + 8];
        const uint32_t a3 = *(const uint32_t*)&xs[g + 8][klo + 8];

        #pragma unroll
        for (int t = 0; t < 8; ++t) {
            const __half2 b0 = dq16(w0[t], sh8, s2[t]);   // k 2c,2c+1
            const __half2 b1 = dq16(w1[t], sh8, s2[t]);   // k 2c+8,2c+9
            hmma16816(acc[t], a0, a1, a2, a3,
                      *(const uint32_t*)&b0, *(const uint32_t*)&b1);
        }

        #pragma unroll
        for (int t = 0; t < 8; ++t) { w0[t] = wn0[t]; w1[t] = wn1[t]; }
    }

    // ---- epilogue: write K-split partials ----
    const size_t pbase = (size_t)blockIdx.y * MM * NN;
    #pragma unroll
    for (int t = 0; t < 8; ++t) {
        const int n = wb + t * 8 + c * 2;
        *(float2*)&g_part[pbase + (size_t)g * NN + n]       = make_float2(acc[t][0], acc[t][1]);
        *(float2*)&g_part[pbase + (size_t)(g + 8) * NN + n] = make_float2(acc[t][2], acc[t][3]);
    }
}

// ---------------- stage 2: vectorized sum of 16 K-split partials ----------------
__global__ void __launch_bounds__(256)
fp4hmma_reduce(float* __restrict__ out)
{
    const int i4 = (blockIdx.x * 256 + threadIdx.x) * 4;   // 4 consecutive outputs
    float4 s = make_float4(0.f, 0.f, 0.f, 0.f);
    #pragma unroll
    for (int i = 0; i < KSPLIT; ++i) {
        const float4 v = *(const float4*)&g_part[(size_t)i * MM * NN + i4];
        s.x += v.x; s.y += v.y; s.z += v.z; s.w += v.w;
    }
    float4 r;
    r.x = __half2float(__float2half(s.x));
    r.y = __half2float(__float2half(s.y));
    r.z = __half2float(__float2half(s.z));
    r.w = __half2float(__float2half(s.w));
    *(float4*)&out[i4] = r;
}

extern "C" void kernel_launch(void* const* d_in, const int* in_sizes, int n_in,
                              void* d_out, int out_size)
{
    const float* x      = (const float*)d_in[0];
    const int*   wp     = (const int*)  d_in[1];
    const float* scales = (const float*)d_in[2];
    float*       out    = (float*)d_out;

    dim3 grid(NCTA_N, KSPLIT);
    fp4hmma_stage1<<<grid, TPB>>>(x, wp, scales);
    fp4hmma_reduce<<<(MM * NN) / (256 * 4), 256>>>(out);
}

// round 8
// speedup vs baseline: 2.4422x; 1.0814x over previous
#include <cuda_runtime.h>
#include <cuda_fp16.h>
#include <cstdint>

// ---------------- problem constants ----------------
#define MM      16
#define NN      8192
#define KK      8192
#define GS      128
#define KSPLIT  16
#define KRANGE  (KK / KSPLIT)        // 512 k per CTA
#define KBLKS   (KRANGE / 16)        // 32 k16-blocks
#define NGRP    (KRANGE / GS)        // 4 scale groups per CTA
#define TPB     128                  // 4 warps
#define WCOLS   32                   // columns per warp (4 n-tiles of 8)
#define CTACOLS 128
#define NCTA_N  (NN / CTACOLS)       // 64  -> grid = 64 x 16 = 1024 CTAs
#define XS_STRIDE 520                // halves; word-bank (4g+c)%32 distinct

// 16 * 16 * 8192 f32 = 8 MiB K-split partials
__device__ float g_part[(size_t)KSPLIT * MM * NN];

// nibble-pair (2c, 2c+1) -> scaled fp16x2: (q-8) * (0.5*scale)
static __device__ __forceinline__ __half2 dq16(uint32_t w, uint32_t sh8, __half2 s2) {
    uint32_t t;
    asm("bfe.u32 %0, %1, %2, 8;" : "=r"(t) : "r"(w), "r"(sh8));
    uint32_t v;
    asm("lop3.b32 %0, %1, %2, 0x000F000F, 0xA8;" : "=r"(v) : "r"(t), "r"(t << 12));
    v |= 0x64006400u;
    const uint32_t m1032 = 0xE408E408u;   // fp16x2 (-1032, -1032)
    __half2 h = __hadd2(*reinterpret_cast<__half2*>(&v),
                        *reinterpret_cast<const __half2*>(&m1032));
    return __hmul2(h, s2);
}

static __device__ __forceinline__ void hmma16816(float* d, uint32_t a0, uint32_t a1,
                                                 uint32_t a2, uint32_t a3,
                                                 uint32_t b0, uint32_t b1) {
    asm volatile(
        "mma.sync.aligned.m16n8k16.row.col.f32.f16.f16.f32 "
        "{%0,%1,%2,%3}, {%4,%5,%6,%7}, {%8,%9}, {%0,%1,%2,%3};"
        : "+f"(d[0]), "+f"(d[1]), "+f"(d[2]), "+f"(d[3])
        : "r"(a0), "r"(a1), "r"(a2), "r"(a3), "r"(b0), "r"(b1));
}

// profiling pads: make ncu's fixed skip land on stage1
__global__ void pad_a() {}
__global__ void pad_b() {}

// ---------------- stage 1: dequant-to-register + HMMA ----------------
__global__ void __launch_bounds__(TPB, 6)
fp4hmma_stage1(const float* __restrict__ x,       // [16, 8192] f32 (exact fp16 values)
               const int*   __restrict__ wp,      // [1024, 8192] int32 packed FP4
               const float* __restrict__ scales)  // [64, 8192] f32 (exact fp16 values)
{
    __shared__ __align__(16) __half xs[MM][XS_STRIDE];

    const int tid  = threadIdx.x;
    const int wrp  = tid >> 5;        // 0..3
    const int lane = tid & 31;
    const int g    = lane >> 2;       // 0..7
    const int c    = lane & 3;        // 0..3
    const int kb0  = blockIdx.y * KRANGE;

    // ---- stage x slice [16 x 512] as fp16 (exact convert) ----
    #pragma unroll
    for (int it = 0; it < 16; ++it) {
        const int p  = tid + it * TPB;        // float4 slot 0..2047
        const int m  = p >> 7;
        const int k4 = (p & 127) << 2;
        const float4 v = *(const float4*)&x[(size_t)m * KK + kb0 + k4];
        *(__half2*)&xs[m][k4]     = __floats2half2_rn(v.x, v.y);
        *(__half2*)&xs[m][k4 + 2] = __floats2half2_rn(v.z, v.w);
    }
    __syncthreads();

    const int wb = blockIdx.x * CTACOLS + wrp * WCOLS;

    float acc[4][4];
    #pragma unroll
    for (int t = 0; t < 4; ++t)
        #pragma unroll
        for (int r = 0; r < 4; ++r) acc[t][r] = 0.0f;

    const uint32_t sh8   = (uint32_t)c * 8u;
    const int      prow0 = blockIdx.y * (KRANGE / 8);

    // scale prefetch (group 0)
    float snext[4];
    #pragma unroll
    for (int t = 0; t < 4; ++t)
        snext[t] = scales[(size_t)(blockIdx.y * NGRP) * NN + wb + t * 8 + g];
    __half2 s2[4];

    // weight double-buffer: wA/wB hold 8 words each ({row0 t0..3, row1 t0..3})
    const int* wbase = &wp[(size_t)prow0 * NN + wb + g];
    uint32_t wA[8], wB[8];
    #pragma unroll
    for (int t = 0; t < 4; ++t) {
        wA[t]     = (uint32_t)wbase[t * 8];
        wA[4 + t] = (uint32_t)wbase[(size_t)NN + t * 8];
    }

    #pragma unroll 1
    for (int kb = 0; kb < KBLKS; kb += 2) {
        // group boundary (kb = 0,8,16,24)
        if ((kb & 7) == 0) {
            #pragma unroll
            for (int t = 0; t < 4; ++t)
                s2[t] = __half2half2(__float2half_rn(0.5f * snext[t]));
            const int gn = ((kb >> 3) + 1 < NGRP) ? (kb >> 3) + 1 : (kb >> 3);
            const size_t grow = (size_t)(blockIdx.y * NGRP + gn) * NN;
            #pragma unroll
            for (int t = 0; t < 4; ++t)
                snext[t] = scales[grow + wb + t * 8 + g];
        }

        // prefetch k-block kb+1 into wB
        {
            const int* p = wbase + (size_t)(kb + 1) * 2 * NN;
            #pragma unroll
            for (int t = 0; t < 4; ++t) {
                wB[t]     = (uint32_t)p[t * 8];
                wB[4 + t] = (uint32_t)p[(size_t)NN + t * 8];
            }
        }

        // consume wA (k-block kb)
        {
            const int klo = kb * 16 + c * 2;
            const uint32_t a0 = *(const uint32_t*)&xs[g][klo];
            const uint32_t a1 = *(const uint32_t*)&xs[g + 8][klo];
            const uint32_t a2 = *(const uint32_t*)&xs[g][klo + 8];
            const uint32_t a3 = *(const uint32_t*)&xs[g + 8][klo + 8];
            #pragma unroll
            for (int t = 0; t < 4; ++t) {
                const __half2 b0 = dq16(wA[t], sh8, s2[t]);
                const __half2 b1 = dq16(wA[4 + t], sh8, s2[t]);
                hmma16816(acc[t], a0, a1, a2, a3,
                          *(const uint32_t*)&b0, *(const uint32_t*)&b1);
            }
        }

        // prefetch k-block kb+2 into wA (clamped on the last macro-iter)
        {
            const int kbn = (kb + 2 < KBLKS) ? kb + 2 : kb;
            const int* p = wbase + (size_t)kbn * 2 * NN;
            #pragma unroll
            for (int t = 0; t < 4; ++t) {
                wA[t]     = (uint32_t)p[t * 8];
                wA[4 + t] = (uint32_t)p[(size_t)NN + t * 8];
            }
        }

        // consume wB (k-block kb+1)
        {
            const int klo = (kb + 1) * 16 + c * 2;
            const uint32_t a0 = *(const uint32_t*)&xs[g][klo];
            const uint32_t a1 = *(const uint32_t*)&xs[g + 8][klo];
            const uint32_t a2 = *(const uint32_t*)&xs[g][klo + 8];
            const uint32_t a3 = *(const uint32_t*)&xs[g + 8][klo + 8];
            #pragma unroll
            for (int t = 0; t < 4; ++t) {
                const __half2 b0 = dq16(wB[t], sh8, s2[t]);
                const __half2 b1 = dq16(wB[4 + t], sh8, s2[t]);
                hmma16816(acc[t], a0, a1, a2, a3,
                          *(const uint32_t*)&b0, *(const uint32_t*)&b1);
            }
        }
    }

    // ---- epilogue: write K-split partials ----
    const size_t pbase = (size_t)blockIdx.y * MM * NN;
    #pragma unroll
    for (int t = 0; t < 4; ++t) {
        const int n = wb + t * 8 + c * 2;
        *(float2*)&g_part[pbase + (size_t)g * NN + n]       = make_float2(acc[t][0], acc[t][1]);
        *(float2*)&g_part[pbase + (size_t)(g + 8) * NN + n] = make_float2(acc[t][2], acc[t][3]);
    }
}

// ---------------- stage 2: 16 in-flight loads, tree sum ----------------
__global__ void __launch_bounds__(256)
fp4hmma_reduce(float* __restrict__ out)
{
    const int idx = blockIdx.x * 256 + threadIdx.x;   // m*NN + n
    float v[KSPLIT];
    #pragma unroll
    for (int i = 0; i < KSPLIT; ++i)
        v[i] = g_part[(size_t)i * MM * NN + idx];
    // pairwise tree: keeps all 16 loads in flight, deterministic order
    #pragma unroll
    for (int stride = 1; stride < KSPLIT; stride <<= 1)
        #pragma unroll
        for (int i = 0; i < KSPLIT; i += 2 * stride)
            v[i] += v[i + stride];
    out[idx] = __half2float(__float2half(v[0]));
}

extern "C" void kernel_launch(void* const* d_in, const int* in_sizes, int n_in,
                              void* d_out, int out_size)
{
    const float* x      = (const float*)d_in[0];
    const int*   wp     = (const int*)  d_in[1];
    const float* scales = (const float*)d_in[2];
    float*       out    = (float*)d_out;

    dim3 grid(NCTA_N, KSPLIT);
    pad_a<<<1, 32>>>();                       // launch-order pads so ncu's
    fp4hmma_stage1<<<grid, TPB>>>(x, wp, scales);
    pad_b<<<1, 32>>>();                       // fixed skip lands on stage1
    fp4hmma_reduce<<<(MM * NN) / 256, 256>>>(out);
}

// round 9
// speedup vs baseline: 2.8764x; 1.1778x over previous
#include <cuda_runtime.h>
#include <cuda_fp16.h>
#include <cstdint>

// ---------------- problem constants ----------------
#define MM      16
#define NN      8192
#define KK      8192
#define GS      128
#define KSPLIT  16
#define KRANGE  (KK / KSPLIT)        // 512 k per CTA
#define KBLKS   (KRANGE / 16)        // 32 k16-blocks
#define NGRP    (KRANGE / GS)        // 4 scale groups per CTA
#define TPB     128                  // 4 warps
#define WCOLS   32                   // columns per warp (4 n-tiles of 8)
#define CTACOLS 128
#define NCTA_N  (NN / CTACOLS)       // 64  -> grid = 64 x 16 = 1024 CTAs
#define XS_STRIDE 520                // halves; word-bank (4g+c)%32 distinct

// 16 * 16 * 8192 f32 = 8 MiB K-split partials
__device__ float g_part[(size_t)KSPLIT * MM * NN];

// k-permuted dequant: ((w >> 4c) & 0x000F000F) | 0x64006400 gives fp16x2
// (1024+q[c], 1024+q[c+4]) in ONE LOP3 after the shift.  Slots (2c,2c+1)
// carry k=(c,c+4); x is staged into SMEM with the matching permutation.
static __device__ __forceinline__ __half2 dq4(uint32_t w, uint32_t sh4, __half2 s2) {
    uint32_t v;
    const uint32_t t = w >> sh4;
    // v = (t & 0x000F000F) | 0x64006400   (LUT 0xEA = (a&b)|c)
    asm("lop3.b32 %0, %1, 0x000F000F, 0x64006400, 0xEA;" : "=r"(v) : "r"(t));
    const uint32_t m1032 = 0xE408E408u;   // fp16x2 (-1032, -1032)
    __half2 h = __hadd2(*reinterpret_cast<__half2*>(&v),
                        *reinterpret_cast<const __half2*>(&m1032)); // (q-8) exact
    return __hmul2(h, s2);
}

static __device__ __forceinline__ void hmma16816(float* d, uint32_t a0, uint32_t a1,
                                                 uint32_t a2, uint32_t a3,
                                                 uint32_t b0, uint32_t b1) {
    asm volatile(
        "mma.sync.aligned.m16n8k16.row.col.f32.f16.f16.f32 "
        "{%0,%1,%2,%3}, {%4,%5,%6,%7}, {%8,%9}, {%0,%1,%2,%3};"
        : "+f"(d[0]), "+f"(d[1]), "+f"(d[2]), "+f"(d[3])
        : "r"(a0), "r"(a1), "r"(a2), "r"(a3), "r"(b0), "r"(b1));
}

// ---------------- stage 1: dequant-to-register + HMMA ----------------
__global__ void __launch_bounds__(TPB, 6)
fp4hmma_stage1(const float* __restrict__ x,       // [16, 8192] f32 (exact fp16 values)
               const int*   __restrict__ wp,      // [1024, 8192] int32 packed FP4
               const float* __restrict__ scales)  // [64, 8192] f32 (exact fp16 values)
{
    __shared__ __align__(16) __half xs[MM][XS_STRIDE];

    const int tid  = threadIdx.x;
    const int wrp  = tid >> 5;        // 0..3
    const int lane = tid & 31;
    const int g    = lane >> 2;       // 0..7
    const int c    = lane & 3;        // 0..3
    const int kb0  = blockIdx.y * KRANGE;

    // ---- stage x slice [16 x 512] as fp16, k-PERMUTED per 8-k sub-block:
    // position 2j holds k=j, position 2j+1 holds k=j+4  (j = 0..3)
    #pragma unroll
    for (int it = 0; it < 8; ++it) {
        const int p  = tid + it * TPB;        // 8-float chunk id 0..1023
        const int m  = p >> 6;                // 64 chunks per row
        const int k8 = (p & 63) << 3;
        const float4 va = *(const float4*)&x[(size_t)m * KK + kb0 + k8];
        const float4 vb = *(const float4*)&x[(size_t)m * KK + kb0 + k8 + 4];
        *(__half2*)&xs[m][k8]     = __floats2half2_rn(va.x, vb.x);
        *(__half2*)&xs[m][k8 + 2] = __floats2half2_rn(va.y, vb.y);
        *(__half2*)&xs[m][k8 + 4] = __floats2half2_rn(va.z, vb.z);
        *(__half2*)&xs[m][k8 + 6] = __floats2half2_rn(va.w, vb.w);
    }
    __syncthreads();

    const int wb = blockIdx.x * CTACOLS + wrp * WCOLS;

    float acc[4][4];
    #pragma unroll
    for (int t = 0; t < 4; ++t)
        #pragma unroll
        for (int r = 0; r < 4; ++r) acc[t][r] = 0.0f;

    const uint32_t sh4   = (uint32_t)c * 4u;
    const int      prow0 = blockIdx.y * (KRANGE / 8);

    float snext[4];
    #pragma unroll
    for (int t = 0; t < 4; ++t)
        snext[t] = scales[(size_t)(blockIdx.y * NGRP) * NN + wb + t * 8 + g];
    __half2 s2[4];

    // weight double-buffer: wA/wB hold 8 words ({row0 t0..3, row1 t0..3})
    const int* wbase = &wp[(size_t)prow0 * NN + wb + g];
    uint32_t wA[8], wB[8];
    #pragma unroll
    for (int t = 0; t < 4; ++t) {
        wA[t]     = (uint32_t)wbase[t * 8];
        wA[4 + t] = (uint32_t)wbase[(size_t)NN + t * 8];
    }

    #pragma unroll 1
    for (int kb = 0; kb < KBLKS; kb += 2) {
        if ((kb & 7) == 0) {
            #pragma unroll
            for (int t = 0; t < 4; ++t)
                s2[t] = __half2half2(__float2half_rn(0.5f * snext[t]));
            const int gn = ((kb >> 3) + 1 < NGRP) ? (kb >> 3) + 1 : (kb >> 3);
            const size_t grow = (size_t)(blockIdx.y * NGRP + gn) * NN;
            #pragma unroll
            for (int t = 0; t < 4; ++t)
                snext[t] = scales[grow + wb + t * 8 + g];
        }

        // prefetch k-block kb+1 into wB
        {
            const int* p = wbase + (size_t)(kb + 1) * 2 * NN;
            #pragma unroll
            for (int t = 0; t < 4; ++t) {
                wB[t]     = (uint32_t)p[t * 8];
                wB[4 + t] = (uint32_t)p[(size_t)NN + t * 8];
            }
        }

        // consume wA (k-block kb)
        {
            const int klo = kb * 16 + c * 2;
            const uint32_t a0 = *(const uint32_t*)&xs[g][klo];
            const uint32_t a1 = *(const uint32_t*)&xs[g + 8][klo];
            const uint32_t a2 = *(const uint32_t*)&xs[g][klo + 8];
            const uint32_t a3 = *(const uint32_t*)&xs[g + 8][klo + 8];
            #pragma unroll
            for (int t = 0; t < 4; ++t) {
                const __half2 b0 = dq4(wA[t], sh4, s2[t]);
                const __half2 b1 = dq4(wA[4 + t], sh4, s2[t]);
                hmma16816(acc[t], a0, a1, a2, a3,
                          *(const uint32_t*)&b0, *(const uint32_t*)&b1);
            }
        }

        // prefetch k-block kb+2 into wA (clamped)
        {
            const int kbn = (kb + 2 < KBLKS) ? kb + 2 : kb;
            const int* p = wbase + (size_t)kbn * 2 * NN;
            #pragma unroll
            for (int t = 0; t < 4; ++t) {
                wA[t]     = (uint32_t)p[t * 8];
                wA[4 + t] = (uint32_t)p[(size_t)NN + t * 8];
            }
        }

        // consume wB (k-block kb+1)
        {
            const int klo = (kb + 1) * 16 + c * 2;
            const uint32_t a0 = *(const uint32_t*)&xs[g][klo];
            const uint32_t a1 = *(const uint32_t*)&xs[g + 8][klo];
            const uint32_t a2 = *(const uint32_t*)&xs[g][klo + 8];
            const uint32_t a3 = *(const uint32_t*)&xs[g + 8][klo + 8];
            #pragma unroll
            for (int t = 0; t < 4; ++t) {
                const __half2 b0 = dq4(wB[t], sh4, s2[t]);
                const __half2 b1 = dq4(wB[4 + t], sh4, s2[t]);
                hmma16816(acc[t], a0, a1, a2, a3,
                          *(const uint32_t*)&b0, *(const uint32_t*)&b1);
            }
        }
    }

    // ---- epilogue: write K-split partials ----
    const size_t pbase = (size_t)blockIdx.y * MM * NN;
    #pragma unroll
    for (int t = 0; t < 4; ++t) {
        const int n = wb + t * 8 + c * 2;
        *(float2*)&g_part[pbase + (size_t)g * NN + n]       = make_float2(acc[t][0], acc[t][1]);
        *(float2*)&g_part[pbase + (size_t)(g + 8) * NN + n] = make_float2(acc[t][2], acc[t][3]);
    }
}

// ---------------- stage 2: float2 loads, tree sum ----------------
__global__ void __launch_bounds__(256)
fp4hmma_reduce(float* __restrict__ out)
{
    const int i2 = (blockIdx.x * 256 + threadIdx.x) * 2;   // 2 consecutive outputs
    float2 v[KSPLIT];
    #pragma unroll
    for (int i = 0; i < KSPLIT; ++i)
        v[i] = *(const float2*)&g_part[(size_t)i * MM * NN + i2];
    #pragma unroll
    for (int stride = 1; stride < KSPLIT; stride <<= 1)
        #pragma unroll
        for (int i = 0; i < KSPLIT; i += 2 * stride) {
            v[i].x += v[i + stride].x;
            v[i].y += v[i + stride].y;
        }
    float2 r;
    r.x = __half2float(__float2half(v[0].x));
    r.y = __half2float(__float2half(v[0].y));
    *(float2*)&out[i2] = r;
}

extern "C" void kernel_launch(void* const* d_in, const int* in_sizes, int n_in,
                              void* d_out, int out_size)
{
    const float* x      = (const float*)d_in[0];
    const int*   wp     = (const int*)  d_in[1];
    const float* scales = (const float*)d_in[2];
    float*       out    = (float*)d_out;

    dim3 grid(NCTA_N, KSPLIT);
    fp4hmma_stage1<<<grid, TPB>>>(x, wp, scales);
    fp4hmma_reduce<<<(MM * NN) / (256 * 2), 256>>>(out);
}